// round 4
// baseline (speedup 1.0000x reference)
#include <cuda_runtime.h>
#include <cuda_bf16.h>
#include <math_constants.h>

// EdgeAwareLoss: predictions [16,19,512,512] f32, targets [16,512,512] int32
// (JAX default x64-disabled demotes int64 -> int32; harness passes int32).
// out: scalar f32 = mean over pixels of CE * (1 + edge)
// edge = (3x3 window max != min) over labels, SAME with +-inf pad
//      = any in-bounds neighbor label != center label.

#define BB 16
#define CC 19
#define HH 512
#define WW 512
#define HW (HH * WW)            // 262144
#define NPIX (BB * HW)          // 4194304
#define TPB 256
#define NBLK (NPIX / TPB)       // 16384

__device__ double g_partials[NBLK];

__global__ __launch_bounds__(TPB) void edge_loss_main(
    const float* __restrict__ pred, const int* __restrict__ tgt)
{
    const int idx = blockIdx.x * TPB + threadIdx.x;
    const int hw = idx & (HW - 1);
    const int b  = idx >> 18;
    const int h  = hw >> 9;
    const int w  = hw & (WW - 1);

    // ---- channel values: 19 coalesced strided loads, kept in registers ----
    const float* p = pred + b * (CC * HW) + hw;
    float v[CC];
    float m = -CUDART_INF_F;
#pragma unroll
    for (int c = 0; c < CC; ++c) {
        v[c] = p[c * HW];
        m = fmaxf(m, v[c]);
    }
    float s = 0.f;
#pragma unroll
    for (int c = 0; c < CC; ++c) s += __expf(v[c] - m);
    const float lse = m + __logf(s);

    // ---- target + gather v[t] without dynamic register indexing ----
    const int* tb = tgt + b * HW;
    const int t = tb[hw];
    float xt = v[0];
#pragma unroll
    for (int c = 1; c < CC; ++c) xt = (t == c) ? v[c] : xt;
    const float ce = lse - xt;

    // ---- edge mask: any in-bounds 3x3 neighbor differs from center ----
    int edge = 0;
#pragma unroll
    for (int dh = -1; dh <= 1; ++dh) {
        const int hh = h + dh;
        if ((unsigned)hh >= (unsigned)HH) continue;
        const int* row = tb + hh * WW;
#pragma unroll
        for (int dw = -1; dw <= 1; ++dw) {
            const int ww = w + dw;
            if ((unsigned)ww >= (unsigned)WW) continue;
            edge |= (row[ww] != t);
        }
    }

    float val = ce * (edge ? 2.0f : 1.0f);

    // ---- block reduction -> g_partials[blockIdx.x] (always overwritten) ----
#pragma unroll
    for (int o = 16; o > 0; o >>= 1) val += __shfl_xor_sync(0xFFFFFFFFu, val, o);

    __shared__ float smem[TPB / 32];
    if ((threadIdx.x & 31) == 0) smem[threadIdx.x >> 5] = val;
    __syncthreads();
    if (threadIdx.x < (TPB / 32)) {
        float x = smem[threadIdx.x];
#pragma unroll
        for (int o = (TPB / 64); o > 0; o >>= 1)
            x += __shfl_xor_sync(0xFFu, x, o);
        if (threadIdx.x == 0) g_partials[blockIdx.x] = (double)x;
    }
}

__global__ __launch_bounds__(TPB) void edge_loss_reduce(float* __restrict__ out)
{
    double s = 0.0;
    for (int i = threadIdx.x; i < NBLK; i += TPB) s += g_partials[i];

#pragma unroll
    for (int o = 16; o > 0; o >>= 1) s += __shfl_xor_sync(0xFFFFFFFFu, s, o);

    __shared__ double smem[TPB / 32];
    if ((threadIdx.x & 31) == 0) smem[threadIdx.x >> 5] = s;
    __syncthreads();
    if (threadIdx.x < (TPB / 32)) {
        double x = smem[threadIdx.x];
#pragma unroll
        for (int o = (TPB / 64); o > 0; o >>= 1)
            x += __shfl_xor_sync(0xFFu, x, o);
        if (threadIdx.x == 0) out[0] = (float)(x / (double)NPIX);
    }
}

extern "C" void kernel_launch(void* const* d_in, const int* in_sizes, int n_in,
                              void* d_out, int out_size)
{
    const float* pred = (const float*)d_in[0];
    const int*   tgt  = (const int*)d_in[1];
    float*       out  = (float*)d_out;

    edge_loss_main<<<NBLK, TPB>>>(pred, tgt);
    edge_loss_reduce<<<1, TPB>>>(out);
}